// round 3
// baseline (speedup 1.0000x reference)
#include <cuda_runtime.h>
#include <cstdint>
#include <cstddef>

// ---------------------------------------------------------------------------
// MessagePassing, R3: transform GEMMs use packed fma.rn.f32x2 (2 atoms/thread,
// duplicated weights in smem -> ld.shared.v2.b64 gives packed operands free).
//   transform:  T[v, c] = sum_j x[v,j] * Wrow_c[j]   (c = k*64+i, + bias group)
//   scatter:    m[i] = T[src, K*64+i] + sum_k feat[e,k]*T[src,k*64+i] -> atomicAdd
//   GRU pass1:  gi = a @ wi^T + bi  (same transform, transposed out [192][N])
//   GRU pass2:  gh dots + gates fused
// ---------------------------------------------------------------------------

#define MAX_ATOMS 30720
typedef unsigned long long ull;

__device__ float g_h [(size_t)MAX_ATOMS * 64];
__device__ float g_a [(size_t)MAX_ATOMS * 64];
__device__ float g_b [(size_t)MAX_ATOMS * 64];
__device__ float g_T [(size_t)MAX_ATOMS * 1088];
__device__ float g_gi[(size_t)MAX_ATOMS * 192];

// dynamic smem layout (floats):
//   Xs2  : 64 * 129 float2  = 16512 floats  (x-pairs, padded; reused as stage)
//   Wd   : 32 * 128 floats  (weights duplicated {w,w})
#define XS2_F   (64 * 129 * 2)
#define SMEM_BYTES ((XS2_F + 32 * 128) * 4)

// ---------------------------------------------------------------------------
template <bool TRANS>
__global__ void __launch_bounds__(128)
transform2_kernel(const float* __restrict__ X,
                  const float* __restrict__ W1, int ncols1,
                  const float* __restrict__ W2,
                  const float* __restrict__ bias,
                  float* __restrict__ T, int tpitch,
                  float* __restrict__ zero_out,
                  int natoms)
{
    extern __shared__ float smem[];
    float* Xs2 = smem;                 // float2 view: [j][129], pairs (lo,hi)
    float* Wd  = smem + XS2_F;         // [c][128] duplicated weights

    const int tid = threadIdx.x;
    const int a0  = blockIdx.x * 256;
    const int c0  = blockIdx.y * 32;

    // ---- load X tile: 256 atoms x 64 dims, packed (t, t+128) into float2 ----
    for (int idx = tid; idx < 256 * 64; idx += 128) {
        int r = idx >> 6, j = idx & 63;
        int v = a0 + r;
        float val = (v < natoms) ? X[(size_t)v * 64 + j] : 0.f;
        int rl = r & 127;
        // float2 Xs2[j*129 + rl]: .x for r<128, .y for r>=128
        Xs2[(j * 129 + rl) * 2 + (r >> 7)] = val;
    }

    // ---- load weight tile duplicated: Wd[c][2j]=Wd[c][2j+1]=w[c0+c][j] ----
    for (int idx = tid; idx < 32 * 64; idx += 128) {
        int c = idx >> 6, j = idx & 63;
        int cg = c0 + c;
        const float* src = (cg < ncols1) ? (W1 + (size_t)cg * 64)
                                         : (W2 + (size_t)(cg - ncols1) * 64);
        float w = src[j];
        Wd[c * 128 + 2 * j]     = w;
        Wd[c * 128 + 2 * j + 1] = w;
    }
    __syncthreads();

    // ---- x pairs -> registers (64 packed b64) ----
    ull xp[64];
#pragma unroll
    for (int j = 0; j < 64; ++j)
        xp[j] = *reinterpret_cast<const ull*>(Xs2 + (j * 129 + tid) * 2);
    __syncthreads();   // everyone done reading Xs2 -> safe to reuse as stage

    float* stage = Xs2;
    const uint32_t wd_s = (uint32_t)__cvta_generic_to_shared(Wd);

    for (int c = 0; c < 32; ++c) {
        float bv = bias ? bias[c0 + c] : 0.f;
        ull acc;
        asm("mov.b64 %0, {%1, %1};" : "=l"(acc) : "f"(bv));
        const uint32_t wbase = wd_s + c * 512;
#pragma unroll
        for (int t2 = 0; t2 < 32; ++t2) {
            ull w0, w1;
            asm("ld.shared.v2.b64 {%0, %1}, [%2];"
                : "=l"(w0), "=l"(w1) : "r"(wbase + t2 * 16));
            asm("fma.rn.f32x2 %0, %1, %2, %0;" : "+l"(acc) : "l"(xp[2 * t2]),     "l"(w0));
            asm("fma.rn.f32x2 %0, %1, %2, %0;" : "+l"(acc) : "l"(xp[2 * t2 + 1]), "l"(w1));
        }
        float lo, hi;
        asm("mov.b64 {%0, %1}, %2;" : "=f"(lo), "=f"(hi) : "l"(acc));
        if (TRANS) {
            // stage2[c][257]: atoms contiguous per column
            stage[c * 257 + tid]       = lo;
            stage[c * 257 + 128 + tid] = hi;
        } else {
            // stage[r(256)][33]
            stage[tid * 33 + c]         = lo;
            stage[(tid + 128) * 33 + c] = hi;
        }
    }
    __syncthreads();

    if (TRANS) {
        for (int idx = tid; idx < 32 * 256; idx += 128) {
            int c = idx >> 8, r = idx & 255;
            int v = a0 + r;
            if (v < natoms) T[(size_t)(c0 + c) * natoms + v] = stage[c * 257 + r];
        }
    } else {
        for (int idx = tid; idx < 256 * 32; idx += 128) {
            int r = idx >> 5, c = idx & 31;
            int v = a0 + r;
            if (v < natoms) T[(size_t)v * tpitch + c0 + c] = stage[r * 33 + c];
        }
    }

    if (zero_out != nullptr && c0 == 0) {
        for (int idx = tid; idx < 256 * 64; idx += 128) {
            int r = idx >> 6, j = idx & 63;
            int v = a0 + r;
            if (v < natoms) zero_out[(size_t)v * 64 + j] = 0.f;
        }
    }
}

// ---------------------------------------------------------------------------
template <int KF>
__global__ void __launch_bounds__(256)
scatter_kernel(const float* __restrict__ T, int tpitch,
               const float* __restrict__ feat,
               const int*   __restrict__ idx,
               float*       __restrict__ out,
               int nedges)
{
    const int tid = threadIdx.x;
    const int g = tid >> 6, i = tid & 63;
    const int e = blockIdx.x * 4 + g;
    if (e >= nedges) return;

    const int src = __ldg(&idx[2 * e + 1]);
    const int dst = __ldg(&idx[2 * e + 0]);
    const float* trow = T + (size_t)src * tpitch;

    float f[KF];
#pragma unroll
    for (int kk = 0; kk < KF; ++kk) f[kk] = __ldg(&feat[(size_t)e * KF + kk]);

    float m = __ldg(&trow[KF * 64 + i]);
#pragma unroll
    for (int kk = 0; kk < KF; ++kk)
        m = fmaf(f[kk], __ldg(&trow[kk * 64 + i]), m);

    atomicAdd(&out[(size_t)dst * 64 + i], m);
}

// ---------------------------------------------------------------------------
__global__ void __launch_bounds__(128)
gru_pass2_kernel(const float* __restrict__ hprev,
                 const float* __restrict__ giT,
                 const float* __restrict__ wh,
                 const float* __restrict__ bh,
                 float* __restrict__ hout,
                 int natoms)
{
    __shared__ float Xs[128 * 65];
    const int tid = threadIdx.x;
    const int a0  = blockIdx.x * 128;

    for (int idx = tid; idx < 128 * 64; idx += 128) {
        int r = idx >> 6, j = idx & 63;
        int v = a0 + r;
        Xs[r * 65 + j] = (v < natoms) ? hprev[(size_t)v * 64 + j] : 0.f;
    }
    __syncthreads();

    float x[64];
#pragma unroll
    for (int j = 0; j < 64; ++j) x[j] = Xs[tid * 65 + j];

    const int v  = a0 + tid;
    const int vv = (v < natoms) ? v : 0;

    for (int i = 0; i < 64; ++i) {
        float ar = bh[i], az = bh[64 + i], an = bh[128 + i];
        const float4* wr = reinterpret_cast<const float4*>(wh + (size_t)i * 64);
        const float4* wz = reinterpret_cast<const float4*>(wh + (size_t)(64 + i) * 64);
        const float4* wn = reinterpret_cast<const float4*>(wh + (size_t)(128 + i) * 64);
#pragma unroll
        for (int j4 = 0; j4 < 16; ++j4) {
            float4 a4 = wr[j4], b4 = wz[j4], c4 = wn[j4];
            ar = fmaf(x[4*j4+0], a4.x, ar); ar = fmaf(x[4*j4+1], a4.y, ar);
            ar = fmaf(x[4*j4+2], a4.z, ar); ar = fmaf(x[4*j4+3], a4.w, ar);
            az = fmaf(x[4*j4+0], b4.x, az); az = fmaf(x[4*j4+1], b4.y, az);
            az = fmaf(x[4*j4+2], b4.z, az); az = fmaf(x[4*j4+3], b4.w, az);
            an = fmaf(x[4*j4+0], c4.x, an); an = fmaf(x[4*j4+1], c4.y, an);
            an = fmaf(x[4*j4+2], c4.z, an); an = fmaf(x[4*j4+3], c4.w, an);
        }
        float gir = giT[(size_t)i         * natoms + vv];
        float giz = giT[(size_t)(64 + i)  * natoms + vv];
        float gin = giT[(size_t)(128 + i) * natoms + vv];

        float r_ = 1.f / (1.f + __expf(-(gir + ar)));
        float z_ = 1.f / (1.f + __expf(-(giz + az)));
        float n_ = tanhf(gin + r_ * an);
        Xs[tid * 65 + i] = (1.f - z_) * n_ + z_ * x[i];
    }
    __syncthreads();

    for (int idx = tid; idx < 128 * 64; idx += 128) {
        int r = idx >> 6, j = idx & 63;
        int v2 = a0 + r;
        if (v2 < natoms) hout[(size_t)v2 * 64 + j] = Xs[r * 65 + j];
    }
}

// ---------------------------------------------------------------------------
extern "C" void kernel_launch(void* const* d_in, const int* in_sizes, int n_in,
                              void* d_out, int out_size)
{
    const float* atom  = (const float*)d_in[0];
    const float* bf    = (const float*)d_in[1];
    const int*   bidx  = (const int*)  d_in[2];
    const float* anf   = (const float*)d_in[3];
    const int*   anidx = (const int*)  d_in[4];
    const float* dif   = (const float*)d_in[5];
    const int*   diidx = (const int*)  d_in[6];
    const float* We    = (const float*)d_in[7];
    const float* be    = (const float*)d_in[8];
    const float* Wa    = (const float*)d_in[9];
    const float* ba    = (const float*)d_in[10];
    const float* Wd    = (const float*)d_in[11];
    const float* bd    = (const float*)d_in[12];
    const float* wi    = (const float*)d_in[13];
    const float* wh    = (const float*)d_in[14];
    const float* bi    = (const float*)d_in[15];
    const float* bh    = (const float*)d_in[16];
    float* out = (float*)d_out;

    const int natoms = in_sizes[0] / 64;
    const int nb = in_sizes[2] / 2;
    const int na = in_sizes[4] / 2;
    const int nd = in_sizes[6] / 2;

    float *pH, *pA, *pB, *pT, *pGI;
    cudaGetSymbolAddress((void**)&pH,  g_h);
    cudaGetSymbolAddress((void**)&pA,  g_a);
    cudaGetSymbolAddress((void**)&pB,  g_b);
    cudaGetSymbolAddress((void**)&pT,  g_T);
    cudaGetSymbolAddress((void**)&pGI, g_gi);

    static bool attr_done = false;
    if (!attr_done) {
        cudaFuncSetAttribute(transform2_kernel<false>,
                             cudaFuncAttributeMaxDynamicSharedMemorySize, SMEM_BYTES);
        cudaFuncSetAttribute(transform2_kernel<true>,
                             cudaFuncAttributeMaxDynamicSharedMemorySize, SMEM_BYTES);
        attr_done = true;
    }

    const int ab2 = (natoms + 255) / 256;
    const int abp = (natoms + 127) / 128;
    dim3 blk(128);

    for (int s = 0; s < 4; ++s) {
        const float* hx = (s == 0) ? atom : pH;

        // ---- message: bonds (k=16, 1088 cols) ----
        transform2_kernel<false><<<dim3(ab2, 1088 / 32), blk, SMEM_BYTES>>>(
            hx, We, 16 * 64, be, nullptr, pT, 1088, pA, natoms);
        scatter_kernel<16><<<(nb + 3) / 4, 256>>>(pT, 1088, bf, bidx, pA, nb);

        // ---- message: angles (k=8, 576 cols) ----
        transform2_kernel<false><<<dim3(ab2, 576 / 32), blk, SMEM_BYTES>>>(
            pA, Wa, 8 * 64, ba, nullptr, pT, 576, pB, natoms);
        scatter_kernel<8><<<(na + 3) / 4, 256>>>(pT, 576, anf, anidx, pB, na);

        // ---- message: dihedrals (k=12, 832 cols) ----
        transform2_kernel<false><<<dim3(ab2, 832 / 32), blk, SMEM_BYTES>>>(
            pB, Wd, 12 * 64, bd, nullptr, pT, 832, pA, natoms);
        scatter_kernel<12><<<(nd + 3) / 4, 256>>>(pT, 832, dif, diidx, pA, nd);

        // ---- GRU ----
        transform2_kernel<true><<<dim3(ab2, 192 / 32), blk, SMEM_BYTES>>>(
            pA, wi, 192, nullptr, bi, pGI, 0, nullptr, natoms);
        float* hout = (s == 3) ? out : pH;
        gru_pass2_kernel<<<abp, blk>>>(hx, pGI, wh, bh, hout, natoms);
    }
}

// round 6
// speedup vs baseline: 1.9766x; 1.9766x over previous
#include <cuda_runtime.h>
#include <cuda_bf16.h>
#include <cstdint>
#include <cstddef>

// ---------------------------------------------------------------------------
// MessagePassing R6: transforms via warp-level mma.sync (bf16 2-way split,
// 3 MMA terms, fp32 accum).  R5 bug fixed: smem tiles now load the FULL
// 32-u32 (64 bf16) K rows (R5 loaded 16 u32 -> NaN from uninit smem).
// ---------------------------------------------------------------------------

#define MAX_ATOMS 30720
#define WTAB_ROWS 2688          // 1088 bonds | 576 angles | 832 dihedrals | 192 gru
typedef uint32_t u32;

__device__ float g_h [(size_t)MAX_ATOMS * 64];
__device__ float g_a [(size_t)MAX_ATOMS * 64];
__device__ float g_b [(size_t)MAX_ATOMS * 64];
__device__ float g_T [(size_t)MAX_ATOMS * 1088];
__device__ float g_gi[(size_t)MAX_ATOMS * 192];
__device__ __nv_bfloat16 g_Whi[(size_t)WTAB_ROWS * 64];
__device__ __nv_bfloat16 g_Wlo[(size_t)WTAB_ROWS * 64];
__device__ __nv_bfloat16 g_Xhi[(size_t)MAX_ATOMS * 64];
__device__ __nv_bfloat16 g_Xlo[(size_t)MAX_ATOMS * 64];

// ---------------------------------------------------------------------------
__device__ __forceinline__ void mma16816(float* d, const u32* a, u32 b0, u32 b1) {
    asm volatile(
        "mma.sync.aligned.m16n8k16.row.col.f32.bf16.bf16.f32 "
        "{%0,%1,%2,%3}, {%4,%5,%6,%7}, {%8,%9}, {%0,%1,%2,%3};"
        : "+f"(d[0]), "+f"(d[1]), "+f"(d[2]), "+f"(d[3])
        : "r"(a[0]), "r"(a[1]), "r"(a[2]), "r"(a[3]), "r"(b0), "r"(b1));
}

// ---------------------------------------------------------------------------
__global__ void prep_weights_kernel(const float* __restrict__ We, const float* __restrict__ be,
                                    const float* __restrict__ Wa, const float* __restrict__ ba,
                                    const float* __restrict__ Wd, const float* __restrict__ bd,
                                    const float* __restrict__ wi,
                                    __nv_bfloat16* __restrict__ Whi,
                                    __nv_bfloat16* __restrict__ Wlo)
{
    int idx = blockIdx.x * 256 + threadIdx.x;
    if (idx >= WTAB_ROWS * 64) return;
    int row = idx >> 6, j = idx & 63;
    const float* src; int r;
    if      (row < 1024) { src = We; r = row; }
    else if (row < 1088) { src = be; r = row - 1024; }
    else if (row < 1600) { src = Wa; r = row - 1088; }
    else if (row < 1664) { src = ba; r = row - 1600; }
    else if (row < 2432) { src = Wd; r = row - 1664; }
    else if (row < 2496) { src = bd; r = row - 2432; }
    else                 { src = wi; r = row - 2496; }
    float x = src[r * 64 + j];
    __nv_bfloat16 hi = __float2bfloat16(x);
    Whi[idx] = hi;
    Wlo[idx] = __float2bfloat16(x - __bfloat162float(hi));
}

// ---------------------------------------------------------------------------
__global__ void prep_x_kernel(const float* __restrict__ X,
                              __nv_bfloat16* __restrict__ Xhi,
                              __nv_bfloat16* __restrict__ Xlo,
                              float* __restrict__ zero_out, int n)
{
    int idx = blockIdx.x * 256 + threadIdx.x;
    if (idx >= n) return;
    float x = X[idx];
    __nv_bfloat16 hi = __float2bfloat16(x);
    Xhi[idx] = hi;
    Xlo[idx] = __float2bfloat16(x - __bfloat162float(hi));
    if (zero_out) zero_out[idx] = 0.f;
}

// ---------------------------------------------------------------------------
// transform: block = 128 atoms x 64 cols, 8 warps (warp = m16 x n64).
// smem rows = 32 u32 of data padded to 36 -> conflict-free fragment reads.
// ---------------------------------------------------------------------------
#define SMEM_U32 ((128 * 36) * 2 + (64 * 36) * 2)   // 13824 u32 = 55296 B

template <bool TRANS>
__global__ void __launch_bounds__(256)
transform_mma_kernel(const __nv_bfloat16* __restrict__ Xhi,
                     const __nv_bfloat16* __restrict__ Xlo,
                     const __nv_bfloat16* __restrict__ Whi,
                     const __nv_bfloat16* __restrict__ Wlo,
                     int wrow0,
                     float* __restrict__ T, int tpitch,
                     const float* __restrict__ bias,
                     int natoms)
{
    extern __shared__ u32 sm[];
    u32* AHI = sm;                  // [128][36], 32 data u32 per row
    u32* ALO = AHI + 128 * 36;
    u32* BHI = ALO + 128 * 36;      // [64][36]
    u32* BLO = BHI + 64 * 36;

    const int tid = threadIdx.x;
    const int a0  = blockIdx.x * 128;
    const int c0  = blockIdx.y * 64;

    // ---- A tile: 128 rows x 32 u32 (FULL 64-bf16 K row) ----
    const u32* Xh32 = reinterpret_cast<const u32*>(Xhi);
    const u32* Xl32 = reinterpret_cast<const u32*>(Xlo);
    for (int idx = tid; idx < 128 * 32; idx += 256) {
        int r = idx >> 5, q = idx & 31;
        int v = a0 + r;
        u32 h = 0, l = 0;
        if (v < natoms) { h = Xh32[(size_t)v * 32 + q]; l = Xl32[(size_t)v * 32 + q]; }
        AHI[r * 36 + q] = h;
        ALO[r * 36 + q] = l;
    }
    // ---- B tile: 64 rows x 32 u32 ----
    const u32* Wh32 = reinterpret_cast<const u32*>(Whi);
    const u32* Wl32 = reinterpret_cast<const u32*>(Wlo);
    for (int idx = tid; idx < 64 * 32; idx += 256) {
        int r = idx >> 5, q = idx & 31;
        size_t wr = (size_t)(wrow0 + c0 + r) * 32 + q;
        BHI[r * 36 + q] = Wh32[wr];
        BLO[r * 36 + q] = Wl32[wr];
    }
    __syncthreads();

    const int wid = tid >> 5, lane = tid & 31;
    const int g = lane >> 2, t = lane & 3;
    const int mo = wid * 16;

    float acc[8][4];
#pragma unroll
    for (int nt = 0; nt < 8; ++nt) {
        acc[nt][0] = 0.f; acc[nt][1] = 0.f; acc[nt][2] = 0.f; acc[nt][3] = 0.f;
    }

#pragma unroll
    for (int ks = 0; ks < 4; ++ks) {
        const int kb = ks * 8 + t;                 // u32 col: bf16 k = 16*ks + 2t
        u32 ah[4], al[4];
        ah[0] = AHI[(mo + g)     * 36 + kb];
        ah[1] = AHI[(mo + g + 8) * 36 + kb];
        ah[2] = AHI[(mo + g)     * 36 + kb + 4];   // k + 8
        ah[3] = AHI[(mo + g + 8) * 36 + kb + 4];
        al[0] = ALO[(mo + g)     * 36 + kb];
        al[1] = ALO[(mo + g + 8) * 36 + kb];
        al[2] = ALO[(mo + g)     * 36 + kb + 4];
        al[3] = ALO[(mo + g + 8) * 36 + kb + 4];
#pragma unroll
        for (int nt = 0; nt < 8; ++nt) {
            int br = nt * 8 + g;
            u32 bh0 = BHI[br * 36 + kb], bh1 = BHI[br * 36 + kb + 4];
            u32 bl0 = BLO[br * 36 + kb], bl1 = BLO[br * 36 + kb + 4];
            mma16816(acc[nt], ah, bh0, bh1);   // hi*hi
            mma16816(acc[nt], ah, bl0, bl1);   // hi*lo
            mma16816(acc[nt], al, bh0, bh1);   // lo*hi
        }
    }

    // epilogue: d0=(g,2t), d1=(g,2t+1), d2=(g+8,2t), d3=(g+8,2t+1)
    const int v1 = a0 + mo + g, v2 = v1 + 8;
    if (TRANS) {
#pragma unroll
        for (int nt = 0; nt < 8; ++nt) {
            int c = c0 + nt * 8 + 2 * t;
            float b0 = bias[c], b1 = bias[c + 1];
            if (v1 < natoms) {
                T[(size_t)c * natoms + v1]       = acc[nt][0] + b0;
                T[(size_t)(c + 1) * natoms + v1] = acc[nt][1] + b1;
            }
            if (v2 < natoms) {
                T[(size_t)c * natoms + v2]       = acc[nt][2] + b0;
                T[(size_t)(c + 1) * natoms + v2] = acc[nt][3] + b1;
            }
        }
    } else {
#pragma unroll
        for (int nt = 0; nt < 8; ++nt) {
            int c = c0 + nt * 8 + 2 * t;
            if (v1 < natoms)
                *reinterpret_cast<float2*>(&T[(size_t)v1 * tpitch + c]) =
                    make_float2(acc[nt][0], acc[nt][1]);
            if (v2 < natoms)
                *reinterpret_cast<float2*>(&T[(size_t)v2 * tpitch + c]) =
                    make_float2(acc[nt][2], acc[nt][3]);
        }
    }
}

// ---------------------------------------------------------------------------
template <int KF>
__global__ void __launch_bounds__(256)
scatter_kernel(const float* __restrict__ T, int tpitch,
               const float* __restrict__ feat,
               const int*   __restrict__ idx,
               float*       __restrict__ out,
               int nedges)
{
    const int tid = threadIdx.x;
    const int g = tid >> 6, i = tid & 63;
    const int e = blockIdx.x * 4 + g;
    if (e >= nedges) return;

    const int src = __ldg(&idx[2 * e + 1]);
    const int dst = __ldg(&idx[2 * e + 0]);
    const float* trow = T + (size_t)src * tpitch;

    float f[KF];
#pragma unroll
    for (int kk = 0; kk < KF; ++kk) f[kk] = __ldg(&feat[(size_t)e * KF + kk]);

    float m = __ldg(&trow[KF * 64 + i]);
#pragma unroll
    for (int kk = 0; kk < KF; ++kk)
        m = fmaf(f[kk], __ldg(&trow[kk * 64 + i]), m);

    atomicAdd(&out[(size_t)dst * 64 + i], m);
}

// ---------------------------------------------------------------------------
__global__ void __launch_bounds__(128)
gru_pass2_kernel(const float* __restrict__ hprev,
                 const float* __restrict__ giT,
                 const float* __restrict__ wh,
                 const float* __restrict__ bh,
                 float* __restrict__ hout,
                 int natoms)
{
    __shared__ float Xs[128 * 65];
    const int tid = threadIdx.x;
    const int a0  = blockIdx.x * 128;

    for (int idx = tid; idx < 128 * 64; idx += 128) {
        int r = idx >> 6, j = idx & 63;
        int v = a0 + r;
        Xs[r * 65 + j] = (v < natoms) ? hprev[(size_t)v * 64 + j] : 0.f;
    }
    __syncthreads();

    float x[64];
#pragma unroll
    for (int j = 0; j < 64; ++j) x[j] = Xs[tid * 65 + j];

    const int v  = a0 + tid;
    const int vv = (v < natoms) ? v : 0;

    for (int i = 0; i < 64; ++i) {
        float ar = bh[i], az = bh[64 + i], an = bh[128 + i];
        const float4* wr = reinterpret_cast<const float4*>(wh + (size_t)i * 64);
        const float4* wz = reinterpret_cast<const float4*>(wh + (size_t)(64 + i) * 64);
        const float4* wn = reinterpret_cast<const float4*>(wh + (size_t)(128 + i) * 64);
#pragma unroll
        for (int j4 = 0; j4 < 16; ++j4) {
            float4 a4 = wr[j4], b4 = wz[j4], c4 = wn[j4];
            ar = fmaf(x[4*j4+0], a4.x, ar); ar = fmaf(x[4*j4+1], a4.y, ar);
            ar = fmaf(x[4*j4+2], a4.z, ar); ar = fmaf(x[4*j4+3], a4.w, ar);
            az = fmaf(x[4*j4+0], b4.x, az); az = fmaf(x[4*j4+1], b4.y, az);
            az = fmaf(x[4*j4+2], b4.z, az); az = fmaf(x[4*j4+3], b4.w, az);
            an = fmaf(x[4*j4+0], c4.x, an); an = fmaf(x[4*j4+1], c4.y, an);
            an = fmaf(x[4*j4+2], c4.z, an); an = fmaf(x[4*j4+3], c4.w, an);
        }
        float gir = giT[(size_t)i         * natoms + vv];
        float giz = giT[(size_t)(64 + i)  * natoms + vv];
        float gin = giT[(size_t)(128 + i) * natoms + vv];

        float r_ = 1.f / (1.f + __expf(-(gir + ar)));
        float z_ = 1.f / (1.f + __expf(-(giz + az)));
        float n_ = tanhf(gin + r_ * an);
        Xs[tid * 65 + i] = (1.f - z_) * n_ + z_ * x[i];
    }
    __syncthreads();

    for (int idx = tid; idx < 128 * 64; idx += 128) {
        int r = idx >> 6, j = idx & 63;
        int v2 = a0 + r;
        if (v2 < natoms) hout[(size_t)v2 * 64 + j] = Xs[r * 65 + j];
    }
}

// ---------------------------------------------------------------------------
extern "C" void kernel_launch(void* const* d_in, const int* in_sizes, int n_in,
                              void* d_out, int out_size)
{
    const float* atom  = (const float*)d_in[0];
    const float* bf    = (const float*)d_in[1];
    const int*   bidx  = (const int*)  d_in[2];
    const float* anf   = (const float*)d_in[3];
    const int*   anidx = (const int*)  d_in[4];
    const float* dif   = (const float*)d_in[5];
    const int*   diidx = (const int*)  d_in[6];
    const float* We    = (const float*)d_in[7];
    const float* be    = (const float*)d_in[8];
    const float* Wa    = (const float*)d_in[9];
    const float* ba    = (const float*)d_in[10];
    const float* Wd    = (const float*)d_in[11];
    const float* bd    = (const float*)d_in[12];
    const float* wi    = (const float*)d_in[13];
    const float* wh    = (const float*)d_in[14];
    const float* bi    = (const float*)d_in[15];
    const float* bh    = (const float*)d_in[16];
    float* out = (float*)d_out;

    const int natoms = in_sizes[0] / 64;
    const int nb = in_sizes[2] / 2;
    const int na = in_sizes[4] / 2;
    const int nd = in_sizes[6] / 2;

    float *pH, *pA, *pB, *pT, *pGI;
    __nv_bfloat16 *pWhi, *pWlo, *pXhi, *pXlo;
    cudaGetSymbolAddress((void**)&pH,   g_h);
    cudaGetSymbolAddress((void**)&pA,   g_a);
    cudaGetSymbolAddress((void**)&pB,   g_b);
    cudaGetSymbolAddress((void**)&pT,   g_T);
    cudaGetSymbolAddress((void**)&pGI,  g_gi);
    cudaGetSymbolAddress((void**)&pWhi, g_Whi);
    cudaGetSymbolAddress((void**)&pWlo, g_Wlo);
    cudaGetSymbolAddress((void**)&pXhi, g_Xhi);
    cudaGetSymbolAddress((void**)&pXlo, g_Xlo);

    cudaFuncSetAttribute(transform_mma_kernel<false>,
                         cudaFuncAttributeMaxDynamicSharedMemorySize, SMEM_U32 * 4);
    cudaFuncSetAttribute(transform_mma_kernel<true>,
                         cudaFuncAttributeMaxDynamicSharedMemorySize, SMEM_U32 * 4);

    const int abk = (natoms + 127) / 128;
    const int nx  = natoms * 64;
    const int xg  = (nx + 255) / 256;

    prep_weights_kernel<<<(WTAB_ROWS * 64 + 255) / 256, 256>>>(
        We, be, Wa, ba, Wd, bd, wi, pWhi, pWlo);

    for (int s = 0; s < 4; ++s) {
        const float* hx = (s == 0) ? atom : pH;

        // ---- bonds (weight rows 0..1087) ----
        prep_x_kernel<<<xg, 256>>>(hx, pXhi, pXlo, pA, nx);
        transform_mma_kernel<false><<<dim3(abk, 1088 / 64), 256, SMEM_U32 * 4>>>(
            pXhi, pXlo, pWhi, pWlo, 0, pT, 1088, nullptr, natoms);
        scatter_kernel<16><<<(nb + 3) / 4, 256>>>(pT, 1088, bf, bidx, pA, nb);

        // ---- angles (rows 1088..1663) ----
        prep_x_kernel<<<xg, 256>>>(pA, pXhi, pXlo, pB, nx);
        transform_mma_kernel<false><<<dim3(abk, 576 / 64), 256, SMEM_U32 * 4>>>(
            pXhi, pXlo, pWhi, pWlo, 1088, pT, 576, nullptr, natoms);
        scatter_kernel<8><<<(na + 3) / 4, 256>>>(pT, 576, anf, anidx, pB, na);

        // ---- dihedrals (rows 1664..2495) ----
        prep_x_kernel<<<xg, 256>>>(pB, pXhi, pXlo, pA, nx);
        transform_mma_kernel<false><<<dim3(abk, 832 / 64), 256, SMEM_U32 * 4>>>(
            pXhi, pXlo, pWhi, pWlo, 1664, pT, 832, nullptr, natoms);
        scatter_kernel<12><<<(nd + 3) / 4, 256>>>(pT, 832, dif, diidx, pA, nd);

        // ---- GRU pass1 (rows 2496..2687, transposed out + bi) + pass2 ----
        prep_x_kernel<<<xg, 256>>>(pA, pXhi, pXlo, nullptr, nx);
        transform_mma_kernel<true><<<dim3(abk, 192 / 64), 256, SMEM_U32 * 4>>>(
            pXhi, pXlo, pWhi, pWlo, 2496, pGI, 0, bi, natoms);
        float* hout = (s == 3) ? out : pH;
        gru_pass2_kernel<<<abk, 128>>>(hx, pGI, wh, bh, hout, natoms);
    }
}

// round 7
// speedup vs baseline: 2.2037x; 1.1149x over previous
#include <cuda_runtime.h>
#include <cuda_bf16.h>
#include <cuda_fp16.h>
#include <cstdint>
#include <cstddef>

// ---------------------------------------------------------------------------
// MessagePassing R7: R6 + (1) T stored fp16 -> L2-resident, half traffic;
// (2) scatter reads half2, 32 lanes/edge; (3) h-split fused into GRU epilogue.
// ---------------------------------------------------------------------------

#define MAX_ATOMS 30720
#define WTAB_ROWS 2688          // 1088 bonds | 576 angles | 832 dihedrals | 192 gru
typedef uint32_t u32;

__device__ float g_h [(size_t)MAX_ATOMS * 64];
__device__ float g_a [(size_t)MAX_ATOMS * 64];
__device__ float g_b [(size_t)MAX_ATOMS * 64];
__device__ __half g_T16[(size_t)MAX_ATOMS * 1088];   // 65 MB max -> fits L2
__device__ float g_gi[(size_t)MAX_ATOMS * 192];
__device__ __nv_bfloat16 g_Whi[(size_t)WTAB_ROWS * 64];
__device__ __nv_bfloat16 g_Wlo[(size_t)WTAB_ROWS * 64];
__device__ __nv_bfloat16 g_Xhi[(size_t)MAX_ATOMS * 64];
__device__ __nv_bfloat16 g_Xlo[(size_t)MAX_ATOMS * 64];

// ---------------------------------------------------------------------------
__device__ __forceinline__ void mma16816(float* d, const u32* a, u32 b0, u32 b1) {
    asm volatile(
        "mma.sync.aligned.m16n8k16.row.col.f32.bf16.bf16.f32 "
        "{%0,%1,%2,%3}, {%4,%5,%6,%7}, {%8,%9}, {%0,%1,%2,%3};"
        : "+f"(d[0]), "+f"(d[1]), "+f"(d[2]), "+f"(d[3])
        : "r"(a[0]), "r"(a[1]), "r"(a[2]), "r"(a[3]), "r"(b0), "r"(b1));
}

// ---------------------------------------------------------------------------
__global__ void prep_weights_kernel(const float* __restrict__ We, const float* __restrict__ be,
                                    const float* __restrict__ Wa, const float* __restrict__ ba,
                                    const float* __restrict__ Wd, const float* __restrict__ bd,
                                    const float* __restrict__ wi,
                                    __nv_bfloat16* __restrict__ Whi,
                                    __nv_bfloat16* __restrict__ Wlo)
{
    int idx = blockIdx.x * 256 + threadIdx.x;
    if (idx >= WTAB_ROWS * 64) return;
    int row = idx >> 6, j = idx & 63;
    const float* src; int r;
    if      (row < 1024) { src = We; r = row; }
    else if (row < 1088) { src = be; r = row - 1024; }
    else if (row < 1600) { src = Wa; r = row - 1088; }
    else if (row < 1664) { src = ba; r = row - 1600; }
    else if (row < 2432) { src = Wd; r = row - 1664; }
    else if (row < 2496) { src = bd; r = row - 2432; }
    else                 { src = wi; r = row - 2496; }
    float x = src[r * 64 + j];
    __nv_bfloat16 hi = __float2bfloat16(x);
    Whi[idx] = hi;
    Wlo[idx] = __float2bfloat16(x - __bfloat162float(hi));
}

// ---------------------------------------------------------------------------
__global__ void prep_x_kernel(const float* __restrict__ X,
                              __nv_bfloat16* __restrict__ Xhi,
                              __nv_bfloat16* __restrict__ Xlo,
                              float* __restrict__ zero_out, int n)
{
    int idx = blockIdx.x * 256 + threadIdx.x;
    if (idx >= n) return;
    float x = X[idx];
    __nv_bfloat16 hi = __float2bfloat16(x);
    Xhi[idx] = hi;
    Xlo[idx] = __float2bfloat16(x - __bfloat162float(hi));
    if (zero_out) zero_out[idx] = 0.f;
}

// ---------------------------------------------------------------------------
// transform: block = 128 atoms x 64 cols, 8 warps (warp = m16 x n64).
// TRANS=false: fp16 output (message T).  TRANS=true: fp32 transposed (gi).
// ---------------------------------------------------------------------------
#define SMEM_U32 ((128 * 36) * 2 + (64 * 36) * 2)   // 13824 u32 = 55296 B

template <bool TRANS>
__global__ void __launch_bounds__(256)
transform_mma_kernel(const __nv_bfloat16* __restrict__ Xhi,
                     const __nv_bfloat16* __restrict__ Xlo,
                     const __nv_bfloat16* __restrict__ Whi,
                     const __nv_bfloat16* __restrict__ Wlo,
                     int wrow0,
                     void* __restrict__ Tout, int tpitch,
                     const float* __restrict__ bias,
                     int natoms)
{
    extern __shared__ u32 sm[];
    u32* AHI = sm;                  // [128][36], 32 data u32 per row
    u32* ALO = AHI + 128 * 36;
    u32* BHI = ALO + 128 * 36;      // [64][36]
    u32* BLO = BHI + 64 * 36;

    const int tid = threadIdx.x;
    const int a0  = blockIdx.x * 128;
    const int c0  = blockIdx.y * 64;

    const u32* Xh32 = reinterpret_cast<const u32*>(Xhi);
    const u32* Xl32 = reinterpret_cast<const u32*>(Xlo);
    for (int idx = tid; idx < 128 * 32; idx += 256) {
        int r = idx >> 5, q = idx & 31;
        int v = a0 + r;
        u32 h = 0, l = 0;
        if (v < natoms) { h = Xh32[(size_t)v * 32 + q]; l = Xl32[(size_t)v * 32 + q]; }
        AHI[r * 36 + q] = h;
        ALO[r * 36 + q] = l;
    }
    const u32* Wh32 = reinterpret_cast<const u32*>(Whi);
    const u32* Wl32 = reinterpret_cast<const u32*>(Wlo);
    for (int idx = tid; idx < 64 * 32; idx += 256) {
        int r = idx >> 5, q = idx & 31;
        size_t wr = (size_t)(wrow0 + c0 + r) * 32 + q;
        BHI[r * 36 + q] = Wh32[wr];
        BLO[r * 36 + q] = Wl32[wr];
    }
    __syncthreads();

    const int wid = tid >> 5, lane = tid & 31;
    const int g = lane >> 2, t = lane & 3;
    const int mo = wid * 16;

    float acc[8][4];
#pragma unroll
    for (int nt = 0; nt < 8; ++nt) {
        acc[nt][0] = 0.f; acc[nt][1] = 0.f; acc[nt][2] = 0.f; acc[nt][3] = 0.f;
    }

#pragma unroll
    for (int ks = 0; ks < 4; ++ks) {
        const int kb = ks * 8 + t;
        u32 ah[4], al[4];
        ah[0] = AHI[(mo + g)     * 36 + kb];
        ah[1] = AHI[(mo + g + 8) * 36 + kb];
        ah[2] = AHI[(mo + g)     * 36 + kb + 4];
        ah[3] = AHI[(mo + g + 8) * 36 + kb + 4];
        al[0] = ALO[(mo + g)     * 36 + kb];
        al[1] = ALO[(mo + g + 8) * 36 + kb];
        al[2] = ALO[(mo + g)     * 36 + kb + 4];
        al[3] = ALO[(mo + g + 8) * 36 + kb + 4];
#pragma unroll
        for (int nt = 0; nt < 8; ++nt) {
            int br = nt * 8 + g;
            u32 bh0 = BHI[br * 36 + kb], bh1 = BHI[br * 36 + kb + 4];
            u32 bl0 = BLO[br * 36 + kb], bl1 = BLO[br * 36 + kb + 4];
            mma16816(acc[nt], ah, bh0, bh1);   // hi*hi
            mma16816(acc[nt], ah, bl0, bl1);   // hi*lo
            mma16816(acc[nt], al, bh0, bh1);   // lo*hi
        }
    }

    // epilogue: d0=(g,2t), d1=(g,2t+1), d2=(g+8,2t), d3=(g+8,2t+1)
    const int v1 = a0 + mo + g, v2 = v1 + 8;
    if (TRANS) {
        float* T = reinterpret_cast<float*>(Tout);
#pragma unroll
        for (int nt = 0; nt < 8; ++nt) {
            int c = c0 + nt * 8 + 2 * t;
            float b0 = bias[c], b1 = bias[c + 1];
            if (v1 < natoms) {
                T[(size_t)c * natoms + v1]       = acc[nt][0] + b0;
                T[(size_t)(c + 1) * natoms + v1] = acc[nt][1] + b1;
            }
            if (v2 < natoms) {
                T[(size_t)c * natoms + v2]       = acc[nt][2] + b0;
                T[(size_t)(c + 1) * natoms + v2] = acc[nt][3] + b1;
            }
        }
    } else {
        __half* T = reinterpret_cast<__half*>(Tout);
#pragma unroll
        for (int nt = 0; nt < 8; ++nt) {
            int c = c0 + nt * 8 + 2 * t;   // even
            if (v1 < natoms)
                *reinterpret_cast<__half2*>(T + (size_t)v1 * tpitch + c) =
                    __float22half2_rn(make_float2(acc[nt][0], acc[nt][1]));
            if (v2 < natoms)
                *reinterpret_cast<__half2*>(T + (size_t)v2 * tpitch + c) =
                    __float22half2_rn(make_float2(acc[nt][2], acc[nt][3]));
        }
    }
}

// ---------------------------------------------------------------------------
// scatter: 32 lanes per edge (lane i2 -> dims 2*i2, 2*i2+1), 8 edges/block.
// ---------------------------------------------------------------------------
template <int KF>
__global__ void __launch_bounds__(256)
scatter_kernel(const __half* __restrict__ T, int tpitch,
               const float* __restrict__ feat,
               const int*   __restrict__ idx,
               float*       __restrict__ out,
               int nedges)
{
    const int tid = threadIdx.x;
    const int g = tid >> 5, i2 = tid & 31;
    const int e = blockIdx.x * 8 + g;
    if (e >= nedges) return;

    const int src = __ldg(&idx[2 * e + 1]);
    const int dst = __ldg(&idx[2 * e + 0]);
    const __half2* trow =
        reinterpret_cast<const __half2*>(T + (size_t)src * tpitch) + i2;

    float f[KF];
#pragma unroll
    for (int kk = 0; kk < KF; ++kk) f[kk] = __ldg(&feat[(size_t)e * KF + kk]);

    float2 b = __half22float2(__ldg(&trow[KF * 32]));   // bias column, weight 1
    float m0 = b.x, m1 = b.y;
#pragma unroll
    for (int kk = 0; kk < KF; ++kk) {
        float2 tv = __half22float2(__ldg(&trow[kk * 32]));
        m0 = fmaf(f[kk], tv.x, m0);
        m1 = fmaf(f[kk], tv.y, m1);
    }

    atomicAdd(&out[(size_t)dst * 64 + 2 * i2],     m0);
    atomicAdd(&out[(size_t)dst * 64 + 2 * i2 + 1], m1);
}

// ---------------------------------------------------------------------------
// GRU pass2; fused: writes hout, optional bf16 hi/lo split of hout, optional
// zeroing of the next scatter accumulator.
// ---------------------------------------------------------------------------
__global__ void __launch_bounds__(128)
gru_pass2_kernel(const float* __restrict__ hprev,
                 const float* __restrict__ giT,
                 const float* __restrict__ wh,
                 const float* __restrict__ bh,
                 float* __restrict__ hout,
                 __nv_bfloat16* __restrict__ xhi,
                 __nv_bfloat16* __restrict__ xlo,
                 float* __restrict__ zero_out,
                 int natoms)
{
    __shared__ float Xs[128 * 65];
    const int tid = threadIdx.x;
    const int a0  = blockIdx.x * 128;

    for (int idx = tid; idx < 128 * 64; idx += 128) {
        int r = idx >> 6, j = idx & 63;
        int v = a0 + r;
        Xs[r * 65 + j] = (v < natoms) ? hprev[(size_t)v * 64 + j] : 0.f;
    }
    __syncthreads();

    float x[64];
#pragma unroll
    for (int j = 0; j < 64; ++j) x[j] = Xs[tid * 65 + j];

    const int v  = a0 + tid;
    const int vv = (v < natoms) ? v : 0;

    for (int i = 0; i < 64; ++i) {
        float ar = bh[i], az = bh[64 + i], an = bh[128 + i];
        const float4* wr = reinterpret_cast<const float4*>(wh + (size_t)i * 64);
        const float4* wz = reinterpret_cast<const float4*>(wh + (size_t)(64 + i) * 64);
        const float4* wn = reinterpret_cast<const float4*>(wh + (size_t)(128 + i) * 64);
#pragma unroll
        for (int j4 = 0; j4 < 16; ++j4) {
            float4 a4 = wr[j4], b4 = wz[j4], c4 = wn[j4];
            ar = fmaf(x[4*j4+0], a4.x, ar); ar = fmaf(x[4*j4+1], a4.y, ar);
            ar = fmaf(x[4*j4+2], a4.z, ar); ar = fmaf(x[4*j4+3], a4.w, ar);
            az = fmaf(x[4*j4+0], b4.x, az); az = fmaf(x[4*j4+1], b4.y, az);
            az = fmaf(x[4*j4+2], b4.z, az); az = fmaf(x[4*j4+3], b4.w, az);
            an = fmaf(x[4*j4+0], c4.x, an); an = fmaf(x[4*j4+1], c4.y, an);
            an = fmaf(x[4*j4+2], c4.z, an); an = fmaf(x[4*j4+3], c4.w, an);
        }
        float gir = giT[(size_t)i         * natoms + vv];
        float giz = giT[(size_t)(64 + i)  * natoms + vv];
        float gin = giT[(size_t)(128 + i) * natoms + vv];

        float r_ = 1.f / (1.f + __expf(-(gir + ar)));
        float z_ = 1.f / (1.f + __expf(-(giz + az)));
        float n_ = tanhf(gin + r_ * an);
        Xs[tid * 65 + i] = (1.f - z_) * n_ + z_ * x[i];
    }
    __syncthreads();

    for (int idx = tid; idx < 128 * 64; idx += 128) {
        int r = idx >> 6, j = idx & 63;
        int v2 = a0 + r;
        if (v2 < natoms) {
            float val = Xs[r * 65 + j];
            size_t o = (size_t)v2 * 64 + j;
            hout[o] = val;
            if (xhi) {
                __nv_bfloat16 hi = __float2bfloat16(val);
                xhi[o] = hi;
                xlo[o] = __float2bfloat16(val - __bfloat162float(hi));
            }
            if (zero_out) zero_out[o] = 0.f;
        }
    }
}

// ---------------------------------------------------------------------------
extern "C" void kernel_launch(void* const* d_in, const int* in_sizes, int n_in,
                              void* d_out, int out_size)
{
    const float* atom  = (const float*)d_in[0];
    const float* bf    = (const float*)d_in[1];
    const int*   bidx  = (const int*)  d_in[2];
    const float* anf   = (const float*)d_in[3];
    const int*   anidx = (const int*)  d_in[4];
    const float* dif   = (const float*)d_in[5];
    const int*   diidx = (const int*)  d_in[6];
    const float* We    = (const float*)d_in[7];
    const float* be    = (const float*)d_in[8];
    const float* Wa    = (const float*)d_in[9];
    const float* ba    = (const float*)d_in[10];
    const float* Wd    = (const float*)d_in[11];
    const float* bd    = (const float*)d_in[12];
    const float* wi    = (const float*)d_in[13];
    const float* wh    = (const float*)d_in[14];
    const float* bi    = (const float*)d_in[15];
    const float* bh    = (const float*)d_in[16];
    float* out = (float*)d_out;

    const int natoms = in_sizes[0] / 64;
    const int nb = in_sizes[2] / 2;
    const int na = in_sizes[4] / 2;
    const int nd = in_sizes[6] / 2;

    float *pH, *pA, *pB, *pGI;
    __half* pT;
    __nv_bfloat16 *pWhi, *pWlo, *pXhi, *pXlo;
    cudaGetSymbolAddress((void**)&pH,   g_h);
    cudaGetSymbolAddress((void**)&pA,   g_a);
    cudaGetSymbolAddress((void**)&pB,   g_b);
    cudaGetSymbolAddress((void**)&pT,   g_T16);
    cudaGetSymbolAddress((void**)&pGI,  g_gi);
    cudaGetSymbolAddress((void**)&pWhi, g_Whi);
    cudaGetSymbolAddress((void**)&pWlo, g_Wlo);
    cudaGetSymbolAddress((void**)&pXhi, g_Xhi);
    cudaGetSymbolAddress((void**)&pXlo, g_Xlo);

    cudaFuncSetAttribute(transform_mma_kernel<false>,
                         cudaFuncAttributeMaxDynamicSharedMemorySize, SMEM_U32 * 4);
    cudaFuncSetAttribute(transform_mma_kernel<true>,
                         cudaFuncAttributeMaxDynamicSharedMemorySize, SMEM_U32 * 4);

    const int abk = (natoms + 127) / 128;
    const int nx  = natoms * 64;
    const int xg  = (nx + 255) / 256;

    prep_weights_kernel<<<(WTAB_ROWS * 64 + 255) / 256, 256>>>(
        We, be, Wa, ba, Wd, bd, wi, pWhi, pWlo);

    for (int s = 0; s < 4; ++s) {
        const float* hx = (s == 0) ? atom : pH;

        // ---- bonds (weight rows 0..1087) ----
        if (s == 0)
            prep_x_kernel<<<xg, 256>>>(atom, pXhi, pXlo, pA, nx);
        // (for s>0, gru_pass2 already produced Xhi/Xlo and zeroed pA)
        transform_mma_kernel<false><<<dim3(abk, 1088 / 64), 256, SMEM_U32 * 4>>>(
            pXhi, pXlo, pWhi, pWlo, 0, pT, 1088, nullptr, natoms);
        scatter_kernel<16><<<(nb + 7) / 8, 256>>>(pT, 1088, bf, bidx, pA, nb);

        // ---- angles (rows 1088..1663) ----
        prep_x_kernel<<<xg, 256>>>(pA, pXhi, pXlo, pB, nx);
        transform_mma_kernel<false><<<dim3(abk, 576 / 64), 256, SMEM_U32 * 4>>>(
            pXhi, pXlo, pWhi, pWlo, 1088, pT, 576, nullptr, natoms);
        scatter_kernel<8><<<(na + 7) / 8, 256>>>(pT, 576, anf, anidx, pB, na);

        // ---- dihedrals (rows 1664..2495) ----
        prep_x_kernel<<<xg, 256>>>(pB, pXhi, pXlo, pA, nx);
        transform_mma_kernel<false><<<dim3(abk, 832 / 64), 256, SMEM_U32 * 4>>>(
            pXhi, pXlo, pWhi, pWlo, 1664, pT, 832, nullptr, natoms);
        scatter_kernel<12><<<(nd + 7) / 8, 256>>>(pT, 832, dif, diidx, pA, nd);

        // ---- GRU pass1 (rows 2496..2687) + fused pass2 ----
        prep_x_kernel<<<xg, 256>>>(pA, pXhi, pXlo, nullptr, nx);
        transform_mma_kernel<true><<<dim3(abk, 192 / 64), 256, SMEM_U32 * 4>>>(
            pXhi, pXlo, pWhi, pWlo, 2496, pGI, 0, bi, natoms);
        const bool last = (s == 3);
        gru_pass2_kernel<<<abk, 128>>>(
            hx, pGI, wh, bh,
            last ? out : pH,
            last ? nullptr : pXhi, last ? nullptr : pXlo,
            last ? nullptr : pA,
            natoms);
    }
}